// round 7
// baseline (speedup 1.0000x reference)
#include <cuda_runtime.h>
#include <cstdint>

#define NFFT 16384
#define DIML 8192
#define DIMD 1024
#define NT   256        // 256 threads, 64 elements per thread

// per-stage twiddle table offsets in smem (float2 units)
#define OT4096 0
#define OT1024 4096
#define OT256  5120
#define OT64   5376
#define OT16   5440
#define OT4    5456
#define NTW    5460

// swizzle: XOR bits[7:6] into bits[1:0], bits[9:8] into bits[3:2].
// Conflict-free for all three access patterns (verified per half-warp phase);
// self-inverse (mask depends only on untouched bits >= 6).
#define SWZ(i) ((i) ^ (((i) >> 6) & 3) ^ ((((i) >> 8) & 3) << 2))

// ---------------- device scratch ----------------
__device__ float2 g_twst[NTW];
__device__ float4 g_H [(size_t)DIMD * NFFT / 2];   // spectrum of h, per-thread-chunk layout
__device__ float2 g_xt[(size_t)DIMD * DIML];       // transposed x, batches packed
__device__ float  g_ht[(size_t)DIMD * DIML];       // transposed h
__device__ float2 g_ys[(size_t)DIMD * DIML];       // transposed scaled output

__device__ __forceinline__ float2 cmul(float2 a, float2 b) {
    return make_float2(a.x * b.x - a.y * b.y, a.x * b.y + a.y * b.x);
}
__device__ __forceinline__ float2 cadd(float2 a, float2 b) { return make_float2(a.x + b.x, a.y + b.y); }
__device__ __forceinline__ float2 csub(float2 a, float2 b) { return make_float2(a.x - b.x, a.y - b.y); }

// DIF forward radix-4 butterfly (in place)
__device__ __forceinline__ void bfly(float2& a, float2& b, float2& c, float2& d) {
    float2 t0 = cadd(a, c), t1 = csub(a, c), t2 = cadd(b, d), t3 = csub(b, d);
    float2 t3s = make_float2(t3.y, -t3.x);     // -i * t3
    a = cadd(t0, t2);
    c = csub(t0, t2);
    b = cadd(t1, t3s);
    d = csub(t1, t3s);
}
// inverse radix-4 butterfly (unnormalized)
__device__ __forceinline__ void ibfly(float2& a, float2& b, float2& c, float2& d) {
    float2 u0 = cadd(a, c), u1 = csub(a, c), u2 = cadd(b, d), u3 = csub(b, d);
    float2 u3s = make_float2(u3.y, -u3.x);
    a = cadd(u0, u2);
    c = csub(u0, u2);
    b = csub(u1, u3s);
    d = cadd(u1, u3s);
}
__device__ __forceinline__ void tw3w(float2& b, float2& c, float2& d,
                                     float2 w1, float2 w2, float2 w3) {
    b = cmul(b, w1); c = cmul(c, w2); d = cmul(d, w3);
}
__device__ __forceinline__ void tw3(float2& b, float2& c, float2& d, float2 w) {
    float2 w2 = cmul(w, w), w3 = cmul(w, w2);
    tw3w(b, c, d, w, w2, w3);
}
__device__ __forceinline__ void itw3(float2& b, float2& c, float2& d, float2 w) {
    float2 wc = make_float2(w.x, -w.y);
    float2 w2 = cmul(wc, wc), w3 = cmul(wc, w2);
    tw3w(b, c, d, wc, w2, w3);
}

// ---------------- twiddle init ----------------
__global__ void twiddle_kernel() {
    const int offs[6] = {OT4096, OT1024, OT256, OT64, OT16, OT4};
    const int ms[6]   = {4096, 1024, 256, 64, 16, 4};
    int si = blockIdx.y;
    int m  = ms[si];
    int r  = blockIdx.x * 256 + threadIdx.x;
    if (r < m) {
        float s, c;
        sincospif(0.5f * (float)r / (float)m, &s, &c);
        g_twst[offs[si] + r] = make_float2(c, -s);
    }
}

// ---------------- transposes ----------------
__global__ __launch_bounds__(256)
void transpose_x_kernel(const float* __restrict__ x) {
    __shared__ float2 tile[32][33];
    const int d0 = blockIdx.x * 32, n0 = blockIdx.y * 32;
    for (int i = threadIdx.y; i < 32; i += 8) {
        const size_t base = (size_t)(n0 + i) * DIMD + d0 + threadIdx.x;
        tile[i][threadIdx.x] = make_float2(x[base], x[base + (size_t)DIML * DIMD]);
    }
    __syncthreads();
    for (int i = threadIdx.y; i < 32; i += 8)
        g_xt[(size_t)(d0 + i) * DIML + n0 + threadIdx.x] = tile[threadIdx.x][i];
}

__global__ __launch_bounds__(256)
void transpose_h_kernel(const float* __restrict__ h) {
    __shared__ float tile[32][33];
    const int d0 = blockIdx.x * 32, n0 = blockIdx.y * 32;
    for (int i = threadIdx.y; i < 32; i += 8)
        tile[i][threadIdx.x] = h[(size_t)(n0 + i) * DIMD + d0 + threadIdx.x];
    __syncthreads();
    for (int i = threadIdx.y; i < 32; i += 8)
        g_ht[(size_t)(d0 + i) * DIML + n0 + threadIdx.x] = tile[threadIdx.x][i];
}

__global__ __launch_bounds__(256)
void transpose_out_kernel(const float* __restrict__ bias, float* __restrict__ y) {
    __shared__ float2 tile[32][33];
    const int n0 = blockIdx.x * 32, d0 = blockIdx.y * 32;
    for (int i = threadIdx.y; i < 32; i += 8)
        tile[i][threadIdx.x] = g_ys[(size_t)(d0 + i) * DIML + n0 + threadIdx.x];
    __syncthreads();
    for (int i = threadIdx.y; i < 32; i += 8) {
        const int d = d0 + threadIdx.x;
        const int n = n0 + i;
        const float bv = __ldg(&bias[d]);
        const float2 v = tile[threadIdx.x][i];
        y[(size_t)n * DIMD + d]          = v.x + bv;
        y[(size_t)(DIML + n) * DIMD + d] = v.y + bv;
    }
}

// ================= level helpers ============================================
// v[c][b][a] holds element index  base0 + sa*a + sb*b + sc*c  of the working set.

// Forward 3 stages on register cube: combine c (stride sc), then b, then a.
// Twiddle indices: stage sc: tw_sc[r_ab], stage sb: tw_sb[r_a], stage sa: tw_sa[0].
// L1: (sa,sb,sc) = (256,1024,4096), r = t + 256a (+1024b); tables OT4096/OT1024/OT256 idx t+...
// L2: (4,16,64), r = s + 4a (+16b); tables OT64/OT16/OT4.

// ---- Level 1 forward: stages 4096, 1024, 256. Element = t +256a +1024b +4096c
__device__ __forceinline__ void level1_fwd(float2 v[4][4][4], const float2* sT, int t) {
    // stage m=4096: combine over c, twiddle OT4096[t + 256a + 1024b]
    #pragma unroll
    for (int b = 0; b < 4; b++)
        #pragma unroll
        for (int a = 0; a < 4; a++) {
            bfly(v[0][b][a], v[1][b][a], v[2][b][a], v[3][b][a]);
            tw3(v[1][b][a], v[2][b][a], v[3][b][a], sT[OT4096 + t + 256 * a + 1024 * b]);
        }
    // stage m=1024: combine over b, twiddle OT1024[t + 256a] (hoist per a)
    #pragma unroll
    for (int a = 0; a < 4; a++) {
        float2 w1 = sT[OT1024 + t + 256 * a];
        float2 w2 = cmul(w1, w1), w3 = cmul(w1, w2);
        #pragma unroll
        for (int c = 0; c < 4; c++) {
            bfly(v[c][0][a], v[c][1][a], v[c][2][a], v[c][3][a]);
            tw3w(v[c][1][a], v[c][2][a], v[c][3][a], w1, w2, w3);
        }
    }
    // stage m=256: combine over a, twiddle OT256[t] (hoist once)
    float2 w1 = sT[OT256 + t];
    float2 w2 = cmul(w1, w1), w3 = cmul(w1, w2);
    #pragma unroll
    for (int c = 0; c < 4; c++)
        #pragma unroll
        for (int b = 0; b < 4; b++) {
            bfly(v[c][b][0], v[c][b][1], v[c][b][2], v[c][b][3]);
            tw3w(v[c][b][1], v[c][b][2], v[c][b][3], w1, w2, w3);
        }
}

// ---- Level 1 inverse: stages 256, 1024, 4096 (exact reverse)
__device__ __forceinline__ void level1_inv(float2 v[4][4][4], const float2* sT, int t) {
    {
        float2 w1 = sT[OT256 + t];
        w1.y = -w1.y;
        float2 w2 = cmul(w1, w1), w3 = cmul(w1, w2);
        #pragma unroll
        for (int c = 0; c < 4; c++)
            #pragma unroll
            for (int b = 0; b < 4; b++) {
                tw3w(v[c][b][1], v[c][b][2], v[c][b][3], w1, w2, w3);
                ibfly(v[c][b][0], v[c][b][1], v[c][b][2], v[c][b][3]);
            }
    }
    #pragma unroll
    for (int a = 0; a < 4; a++) {
        float2 w1 = sT[OT1024 + t + 256 * a];
        w1.y = -w1.y;
        float2 w2 = cmul(w1, w1), w3 = cmul(w1, w2);
        #pragma unroll
        for (int c = 0; c < 4; c++) {
            tw3w(v[c][1][a], v[c][2][a], v[c][3][a], w1, w2, w3);
            ibfly(v[c][0][a], v[c][1][a], v[c][2][a], v[c][3][a]);
        }
    }
    #pragma unroll
    for (int b = 0; b < 4; b++)
        #pragma unroll
        for (int a = 0; a < 4; a++) {
            itw3(v[1][b][a], v[2][b][a], v[3][b][a], sT[OT4096 + t + 256 * a + 1024 * b]);
            ibfly(v[0][b][a], v[1][b][a], v[2][b][a], v[3][b][a]);
        }
}

// ---- Level 2 forward: stages 64, 16, 4. Element = g*256 + s + 4a + 16b + 64c
__device__ __forceinline__ void level2_fwd(float2 v[4][4][4], const float2* sT, int s) {
    #pragma unroll
    for (int b = 0; b < 4; b++)
        #pragma unroll
        for (int a = 0; a < 4; a++) {
            bfly(v[0][b][a], v[1][b][a], v[2][b][a], v[3][b][a]);
            tw3(v[1][b][a], v[2][b][a], v[3][b][a], sT[OT64 + s + 4 * a + 16 * b]);
        }
    #pragma unroll
    for (int a = 0; a < 4; a++) {
        float2 w1 = sT[OT16 + s + 4 * a];
        float2 w2 = cmul(w1, w1), w3 = cmul(w1, w2);
        #pragma unroll
        for (int c = 0; c < 4; c++) {
            bfly(v[c][0][a], v[c][1][a], v[c][2][a], v[c][3][a]);
            tw3w(v[c][1][a], v[c][2][a], v[c][3][a], w1, w2, w3);
        }
    }
    float2 w1 = sT[OT4 + s];
    float2 w2 = cmul(w1, w1), w3 = cmul(w1, w2);
    #pragma unroll
    for (int c = 0; c < 4; c++)
        #pragma unroll
        for (int b = 0; b < 4; b++) {
            bfly(v[c][b][0], v[c][b][1], v[c][b][2], v[c][b][3]);
            tw3w(v[c][b][1], v[c][b][2], v[c][b][3], w1, w2, w3);
        }
}

// ---- Level 2 inverse: stages 4, 16, 64
__device__ __forceinline__ void level2_inv(float2 v[4][4][4], const float2* sT, int s) {
    {
        float2 w1 = sT[OT4 + s];
        w1.y = -w1.y;
        float2 w2 = cmul(w1, w1), w3 = cmul(w1, w2);
        #pragma unroll
        for (int c = 0; c < 4; c++)
            #pragma unroll
            for (int b = 0; b < 4; b++) {
                tw3w(v[c][b][1], v[c][b][2], v[c][b][3], w1, w2, w3);
                ibfly(v[c][b][0], v[c][b][1], v[c][b][2], v[c][b][3]);
            }
    }
    #pragma unroll
    for (int a = 0; a < 4; a++) {
        float2 w1 = sT[OT16 + s + 4 * a];
        w1.y = -w1.y;
        float2 w2 = cmul(w1, w1), w3 = cmul(w1, w2);
        #pragma unroll
        for (int c = 0; c < 4; c++) {
            tw3w(v[c][1][a], v[c][2][a], v[c][3][a], w1, w2, w3);
            ibfly(v[c][0][a], v[c][1][a], v[c][2][a], v[c][3][a]);
        }
    }
    #pragma unroll
    for (int b = 0; b < 4; b++)
        #pragma unroll
        for (int a = 0; a < 4; a++) {
            itw3(v[1][b][a], v[2][b][a], v[3][b][a], sT[OT64 + s + 4 * a + 16 * b]);
            ibfly(v[0][b][a], v[1][b][a], v[2][b][a], v[3][b][a]);
        }
}

// smem <-> register cube for level 2 (base = g*256 + s)
#define L2_LOAD(v, sA, base)                                          \
    _Pragma("unroll") for (int c = 0; c < 4; c++)                     \
    _Pragma("unroll") for (int b = 0; b < 4; b++)                     \
    _Pragma("unroll") for (int a = 0; a < 4; a++)                     \
        v[c][b][a] = sA[SWZ((base) + 4 * a + 16 * b + 64 * c)];
#define L2_STORE(v, sA, base)                                         \
    _Pragma("unroll") for (int c = 0; c < 4; c++)                     \
    _Pragma("unroll") for (int b = 0; b < 4; b++)                     \
    _Pragma("unroll") for (int a = 0; a < 4; a++)                     \
        sA[SWZ((base) + 4 * a + 16 * b + 64 * c)] = v[c][b][a];

// ================= FFT of h: forward only, store spectrum ===================
__global__ __launch_bounds__(NT, 1)
void fft_h_kernel() {
    extern __shared__ float2 sm[];
    float2* sA = sm;
    float2* sT = sm + NFFT;
    const int t = threadIdx.x, d = blockIdx.x;

    for (int j = t; j < NTW; j += NT) sT[j] = g_twst[j];
    __syncthreads();

    // ---- level 1 (global -> regs -> smem) ----
    {
        const float* hp = g_ht + (size_t)d * DIML;
        float2 v[4][4][4];
        #pragma unroll
        for (int c = 0; c < 4; c++)
            #pragma unroll
            for (int b = 0; b < 4; b++)
                #pragma unroll
                for (int a = 0; a < 4; a++) {
                    const int idx = t + 256 * a + 1024 * b + 4096 * c;
                    v[c][b][a] = (c < 2) ? make_float2(hp[idx], 0.0f)
                                         : make_float2(0.0f, 0.0f);
                }
        level1_fwd(v, sT, t);
        #pragma unroll
        for (int c = 0; c < 4; c++)
            #pragma unroll
            for (int b = 0; b < 4; b++)
                #pragma unroll
                for (int a = 0; a < 4; a++)
                    sA[SWZ(t + 256 * a + 1024 * b + 4096 * c)] = v[c][b][a];
    }
    __syncthreads();

    // ---- level 2 ----
    {
        const int base = (t >> 2) * 256 + (t & 3);
        float2 v[4][4][4];
        L2_LOAD(v, sA, base);
        level2_fwd(v, sT, t & 3);
        L2_STORE(v, sA, base);
    }
    __syncthreads();

    // ---- level 3: final stage (m=1) + H store, chunks of 8 ----
    {
        float4* Hd = g_H + (size_t)d * (NFFT / 2) + 32 * t;
        #pragma unroll
        for (int k = 0; k < 8; k++) {
            float2 q[8];
            #pragma unroll
            for (int l = 0; l < 8; l++) q[l] = sA[SWZ(64 * t + 8 * k + l)];
            bfly(q[0], q[1], q[2], q[3]);
            bfly(q[4], q[5], q[6], q[7]);
            Hd[4 * k + 0] = make_float4(q[0].x, q[0].y, q[1].x, q[1].y);
            Hd[4 * k + 1] = make_float4(q[2].x, q[2].y, q[3].x, q[3].y);
            Hd[4 * k + 2] = make_float4(q[4].x, q[4].y, q[5].x, q[5].y);
            Hd[4 * k + 3] = make_float4(q[6].x, q[6].y, q[7].x, q[7].y);
        }
    }
}

// ================= conv: fwd FFT, multiply, inverse FFT =====================
__global__ __launch_bounds__(NT, 1)
void fft_conv_kernel() {
    extern __shared__ float2 sm[];
    float2* sA = sm;
    float2* sT = sm + NFFT;
    const int t = threadIdx.x, d = blockIdx.x;

    for (int j = t; j < NTW; j += NT) sT[j] = g_twst[j];
    __syncthreads();

    // ---- level 1 forward (global -> regs -> smem) ----
    {
        const float2* xp = g_xt + (size_t)d * DIML;
        float2 v[4][4][4];
        #pragma unroll
        for (int c = 0; c < 4; c++)
            #pragma unroll
            for (int b = 0; b < 4; b++)
                #pragma unroll
                for (int a = 0; a < 4; a++) {
                    const int idx = t + 256 * a + 1024 * b + 4096 * c;
                    v[c][b][a] = (c < 2) ? xp[idx] : make_float2(0.0f, 0.0f);
                }
        level1_fwd(v, sT, t);
        #pragma unroll
        for (int c = 0; c < 4; c++)
            #pragma unroll
            for (int b = 0; b < 4; b++)
                #pragma unroll
                for (int a = 0; a < 4; a++)
                    sA[SWZ(t + 256 * a + 1024 * b + 4096 * c)] = v[c][b][a];
    }
    __syncthreads();

    // ---- level 2 forward ----
    {
        const int base = (t >> 2) * 256 + (t & 3);
        float2 v[4][4][4];
        L2_LOAD(v, sA, base);
        level2_fwd(v, sT, t & 3);
        L2_STORE(v, sA, base);
    }
    __syncthreads();

    // ---- level 3: fwd stage 1 + H multiply + inverse stage 1 (chunks of 8) --
    {
        const float4* Hd = g_H + (size_t)d * (NFFT / 2) + 32 * t;
        #pragma unroll
        for (int k = 0; k < 8; k++) {
            float2 q[8];
            #pragma unroll
            for (int l = 0; l < 8; l++) q[l] = sA[SWZ(64 * t + 8 * k + l)];
            bfly(q[0], q[1], q[2], q[3]);
            bfly(q[4], q[5], q[6], q[7]);
            #pragma unroll
            for (int p = 0; p < 4; p++) {
                float4 hv = __ldg(&Hd[4 * k + p]);
                q[2 * p]     = cmul(q[2 * p],     make_float2(hv.x, hv.y));
                q[2 * p + 1] = cmul(q[2 * p + 1], make_float2(hv.z, hv.w));
            }
            ibfly(q[0], q[1], q[2], q[3]);
            ibfly(q[4], q[5], q[6], q[7]);
            #pragma unroll
            for (int l = 0; l < 8; l++) sA[SWZ(64 * t + 8 * k + l)] = q[l];
        }
    }
    __syncthreads();

    // ---- level 2 inverse ----
    {
        const int base = (t >> 2) * 256 + (t & 3);
        float2 v[4][4][4];
        L2_LOAD(v, sA, base);
        level2_inv(v, sT, t & 3);
        L2_STORE(v, sA, base);
    }
    __syncthreads();

    // ---- level 1 inverse (smem -> regs -> global) ----
    {
        float2 v[4][4][4];
        #pragma unroll
        for (int c = 0; c < 4; c++)
            #pragma unroll
            for (int b = 0; b < 4; b++)
                #pragma unroll
                for (int a = 0; a < 4; a++)
                    v[c][b][a] = sA[SWZ(t + 256 * a + 1024 * b + 4096 * c)];
        level1_inv(v, sT, t);
        const float scale = 1.0f / (float)NFFT;
        float2* yp = g_ys + (size_t)d * DIML;
        #pragma unroll
        for (int c = 0; c < 2; c++)
            #pragma unroll
            for (int b = 0; b < 4; b++)
                #pragma unroll
                for (int a = 0; a < 4; a++) {
                    float2 r = v[c][b][a];
                    yp[t + 256 * a + 1024 * b + 4096 * c] =
                        make_float2(r.x * scale, r.y * scale);
                }
    }
}

// ---------------------------------------------------------------------------
extern "C" void kernel_launch(void* const* d_in, const int* in_sizes, int n_in,
                              void* d_out, int out_size) {
    const float* x    = (const float*)d_in[0];
    const float* h    = (const float*)d_in[1];
    const float* bias = (const float*)d_in[2];
    float* y = (float*)d_out;

    const int smem = (NFFT + NTW) * sizeof(float2);  // ~171 KB
    cudaFuncSetAttribute(fft_h_kernel,
                         cudaFuncAttributeMaxDynamicSharedMemorySize, smem);
    cudaFuncSetAttribute(fft_conv_kernel,
                         cudaFuncAttributeMaxDynamicSharedMemorySize, smem);

    twiddle_kernel<<<dim3(16, 6), 256>>>();
    transpose_x_kernel<<<dim3(DIMD / 32, DIML / 32), dim3(32, 8)>>>(x);
    transpose_h_kernel<<<dim3(DIMD / 32, DIML / 32), dim3(32, 8)>>>(h);
    fft_h_kernel<<<DIMD, NT, smem>>>();
    fft_conv_kernel<<<DIMD, NT, smem>>>();
    transpose_out_kernel<<<dim3(DIML / 32, DIMD / 32), dim3(32, 8)>>>(bias, y);
}

// round 9
// speedup vs baseline: 1.4191x; 1.4191x over previous
#include <cuda_runtime.h>
#include <cuda_fp16.h>
#include <cstdint>

#define NFFT 16384
#define DIML 8192
#define DIMD 1024
#define NT   512        // 512 threads, 2 groups of 16 elements per thread

// conflict-killing swizzle for sA: XOR low 4 bits with bits[7:4] (self-inverse)
#define SWZ(i) ((i) ^ (((i) >> 4) & 15))

// smem layout (bytes)
//   sA     : float2[16384]   @ 0        (131072)
//   sH     : half2 [16384]   @ 131072   (65536)
//   sA1024 : float2[1024]    @ 196608   (8192)   W^j,      j<1024 (W = W_16384)
//   sB256  : float2[256]     @ 204800   (2048)   W_256^j,  j<256   (stage-64 tw)
//   sW1024 : float2[256]     @ 206848   (2048)   W_1024^j, j<256   (stage-256 tw)
//   sT16   : float2[16]      @ 208896   (128)    W_64^j            (stage-16 tw)
//   sT4    : float2[4]       @ 209024   (32)     W_16^j            (stage-4 tw)
//   sK4    : float2[4]       @ 209056   (32)     W^{1024j}
#define SMEM_BYTES 209088

// ---------------- device scratch ----------------
__device__ float2 g_xt[(size_t)DIMD * DIML];       // transposed x, batches packed
__device__ float  g_ht[(size_t)DIMD * DIML];       // transposed h
__device__ float2 g_ys[(size_t)DIMD * DIML];       // transposed scaled output

__device__ __forceinline__ float2 cmul(float2 a, float2 b) {
    return make_float2(a.x * b.x - a.y * b.y, a.x * b.y + a.y * b.x);
}
__device__ __forceinline__ float2 cconj(float2 a) { return make_float2(a.x, -a.y); }
__device__ __forceinline__ float2 cadd(float2 a, float2 b) { return make_float2(a.x + b.x, a.y + b.y); }
__device__ __forceinline__ float2 csub(float2 a, float2 b) { return make_float2(a.x - b.x, a.y - b.y); }

// DIF forward radix-4 butterfly (in place)
__device__ __forceinline__ void bfly(float2& a, float2& b, float2& c, float2& d) {
    float2 t0 = cadd(a, c), t1 = csub(a, c), t2 = cadd(b, d), t3 = csub(b, d);
    float2 t3s = make_float2(t3.y, -t3.x);     // -i * t3
    a = cadd(t0, t2);
    c = csub(t0, t2);
    b = cadd(t1, t3s);
    d = csub(t1, t3s);
}
// inverse radix-4 butterfly (unnormalized)
__device__ __forceinline__ void ibfly(float2& a, float2& b, float2& c, float2& d) {
    float2 u0 = cadd(a, c), u1 = csub(a, c), u2 = cadd(b, d), u3 = csub(b, d);
    float2 u3s = make_float2(u3.y, -u3.x);
    a = cadd(u0, u2);
    c = csub(u0, u2);
    b = csub(u1, u3s);
    d = cadd(u1, u3s);
}
__device__ __forceinline__ void tw3w(float2& b, float2& c, float2& d,
                                     float2 w1, float2 w2, float2 w3) {
    b = cmul(b, w1); c = cmul(c, w2); d = cmul(d, w3);
}
__device__ __forceinline__ void tw3(float2& b, float2& c, float2& d, float2 w) {
    float2 w2 = cmul(w, w), w3 = cmul(w, w2);
    tw3w(b, c, d, w, w2, w3);
}
__device__ __forceinline__ void itw3(float2& b, float2& c, float2& d, float2 w) {
    float2 wc = cconj(w);
    float2 w2 = cmul(wc, wc), w3 = cmul(wc, w2);
    tw3w(b, c, d, wc, w2, w3);
}

// ---------------- transposes ----------------
__global__ __launch_bounds__(256)
void transpose_x_kernel(const float* __restrict__ x) {
    __shared__ float2 tile[32][33];
    const int d0 = blockIdx.x * 32, n0 = blockIdx.y * 32;
    for (int i = threadIdx.y; i < 32; i += 8) {
        const size_t base = (size_t)(n0 + i) * DIMD + d0 + threadIdx.x;
        tile[i][threadIdx.x] = make_float2(x[base], x[base + (size_t)DIML * DIMD]);
    }
    __syncthreads();
    for (int i = threadIdx.y; i < 32; i += 8)
        g_xt[(size_t)(d0 + i) * DIML + n0 + threadIdx.x] = tile[threadIdx.x][i];
}

__global__ __launch_bounds__(256)
void transpose_h_kernel(const float* __restrict__ h) {
    __shared__ float tile[32][33];
    const int d0 = blockIdx.x * 32, n0 = blockIdx.y * 32;
    for (int i = threadIdx.y; i < 32; i += 8)
        tile[i][threadIdx.x] = h[(size_t)(n0 + i) * DIMD + d0 + threadIdx.x];
    __syncthreads();
    for (int i = threadIdx.y; i < 32; i += 8)
        g_ht[(size_t)(d0 + i) * DIML + n0 + threadIdx.x] = tile[threadIdx.x][i];
}

__global__ __launch_bounds__(256)
void transpose_out_kernel(const float* __restrict__ bias, float* __restrict__ y) {
    __shared__ float2 tile[32][33];
    const int n0 = blockIdx.x * 32, d0 = blockIdx.y * 32;
    for (int i = threadIdx.y; i < 32; i += 8)
        tile[i][threadIdx.x] = g_ys[(size_t)(d0 + i) * DIML + n0 + threadIdx.x];
    __syncthreads();
    for (int i = threadIdx.y; i < 32; i += 8) {
        const int d = d0 + threadIdx.x;
        const int n = n0 + i;
        const float bv = __ldg(&bias[d]);
        const float2 v = tile[threadIdx.x][i];
        y[(size_t)n * DIMD + d]          = v.x + bv;
        y[(size_t)(DIML + n) * DIMD + d] = v.y + bv;
    }
}

// ================= pass helpers =============================================

// Pass A: stages m=4096, m=1024 on v[a][b] (element t + 1024b + 4096a), t<1024
__device__ __forceinline__ void passA_fwd(float2 v[4][4], const float2* sA1024,
                                          const float2* sK4, int t) {
    const float2 at = sA1024[t];
    #pragma unroll
    for (int b = 0; b < 4; b++) {
        bfly(v[0][b], v[1][b], v[2][b], v[3][b]);
        float2 w = (b == 0) ? at : cmul(at, sK4[b]);   // W^{t+1024b}
        tw3(v[1][b], v[2][b], v[3][b], w);
    }
    float2 w1 = cmul(at, at); w1 = cmul(w1, w1);       // OT1024[t] = at^4
    float2 w2 = cmul(w1, w1), w3 = cmul(w1, w2);
    #pragma unroll
    for (int a = 0; a < 4; a++) {
        bfly(v[a][0], v[a][1], v[a][2], v[a][3]);
        tw3w(v[a][1], v[a][2], v[a][3], w1, w2, w3);
    }
}

// Pass B: stages m=256, m=64. element e(a,b) = u*1024 + rp + 64b + 256a
// stage-256 twiddles: sW1024[rp + 64b]; stage-64: sB256[rp]
__device__ __forceinline__ void passB_fwd(float2* sA, const float2* sW1024,
                                          const float2* sB256, int t) {
    const int u = t >> 6, rp = t & 63;
    const int base = u * 1024 + rp;
    float2 v[4][4];
    #pragma unroll
    for (int a = 0; a < 4; a++)
        #pragma unroll
        for (int b = 0; b < 4; b++)
            v[a][b] = sA[SWZ(base + 64 * b + 256 * a)];
    #pragma unroll
    for (int b = 0; b < 4; b++) {
        bfly(v[0][b], v[1][b], v[2][b], v[3][b]);
        tw3(v[1][b], v[2][b], v[3][b], sW1024[rp + 64 * b]);
    }
    float2 w1 = sB256[rp];
    float2 w2 = cmul(w1, w1), w3 = cmul(w1, w2);
    #pragma unroll
    for (int a = 0; a < 4; a++) {
        bfly(v[a][0], v[a][1], v[a][2], v[a][3]);
        tw3w(v[a][1], v[a][2], v[a][3], w1, w2, w3);
    }
    #pragma unroll
    for (int a = 0; a < 4; a++)
        #pragma unroll
        for (int b = 0; b < 4; b++)
            sA[SWZ(base + 64 * b + 256 * a)] = v[a][b];
}

// Pass C: stage m=16. element e(s,a) = qb*64 + rq + 4096s + 16a
__device__ __forceinline__ void passC_fwd(float2* sA, const float2* sT16, int t) {
    const int rq = t & 15, qb = t >> 4;
    const int base = qb * 64 + rq;
    float2 v[4][4];
    #pragma unroll
    for (int s = 0; s < 4; s++)
        #pragma unroll
        for (int a = 0; a < 4; a++)
            v[s][a] = sA[SWZ(base + 4096 * s + 16 * a)];
    float2 w1 = sT16[rq];
    float2 w2 = cmul(w1, w1), w3 = cmul(w1, w2);
    #pragma unroll
    for (int s = 0; s < 4; s++) {
        bfly(v[s][0], v[s][1], v[s][2], v[s][3]);
        tw3w(v[s][1], v[s][2], v[s][3], w1, w2, w3);
    }
    #pragma unroll
    for (int s = 0; s < 4; s++)
        #pragma unroll
        for (int a = 0; a < 4; a++)
            sA[SWZ(base + 4096 * s + 16 * a)] = v[s][a];
}

// Pass D forward: stages m=4, m=1 on u16 (elements 16t..16t+15)
__device__ __forceinline__ void passD_fwd(float2 u16[16], const float2* sT4) {
    #pragma unroll
    for (int r = 0; r < 4; r++) {
        bfly(u16[r], u16[r + 4], u16[r + 8], u16[r + 12]);
        tw3(u16[r + 4], u16[r + 8], u16[r + 12], sT4[r]);
    }
    #pragma unroll
    for (int g = 0; g < 4; g++)
        bfly(u16[4 * g], u16[4 * g + 1], u16[4 * g + 2], u16[4 * g + 3]);
}

// inverse pass C'
__device__ __forceinline__ void passC_inv(float2* sA, const float2* sT16, int t) {
    const int rq = t & 15, qb = t >> 4;
    const int base = qb * 64 + rq;
    float2 w1 = cconj(sT16[rq]);
    float2 w2 = cmul(w1, w1), w3 = cmul(w1, w2);
    float2 v[4][4];
    #pragma unroll
    for (int s = 0; s < 4; s++)
        #pragma unroll
        for (int a = 0; a < 4; a++)
            v[s][a] = sA[SWZ(base + 4096 * s + 16 * a)];
    #pragma unroll
    for (int s = 0; s < 4; s++) {
        tw3w(v[s][1], v[s][2], v[s][3], w1, w2, w3);
        ibfly(v[s][0], v[s][1], v[s][2], v[s][3]);
    }
    #pragma unroll
    for (int s = 0; s < 4; s++)
        #pragma unroll
        for (int a = 0; a < 4; a++)
            sA[SWZ(base + 4096 * s + 16 * a)] = v[s][a];
}

// inverse pass B'
__device__ __forceinline__ void passB_inv(float2* sA, const float2* sW1024,
                                          const float2* sB256, int t) {
    const int u = t >> 6, rp = t & 63;
    const int base = u * 1024 + rp;
    float2 v[4][4];
    #pragma unroll
    for (int a = 0; a < 4; a++)
        #pragma unroll
        for (int b = 0; b < 4; b++)
            v[a][b] = sA[SWZ(base + 64 * b + 256 * a)];
    float2 w1 = cconj(sB256[rp]);
    float2 w2 = cmul(w1, w1), w3 = cmul(w1, w2);
    #pragma unroll
    for (int a = 0; a < 4; a++) {
        tw3w(v[a][1], v[a][2], v[a][3], w1, w2, w3);
        ibfly(v[a][0], v[a][1], v[a][2], v[a][3]);
    }
    #pragma unroll
    for (int b = 0; b < 4; b++) {
        itw3(v[1][b], v[2][b], v[3][b], sW1024[rp + 64 * b]);
        ibfly(v[0][b], v[1][b], v[2][b], v[3][b]);
    }
    #pragma unroll
    for (int a = 0; a < 4; a++)
        #pragma unroll
        for (int b = 0; b < 4; b++)
            sA[SWZ(base + 64 * b + 256 * a)] = v[a][b];
}

// ================= fused conv: h-FFT (H -> smem fp16) + x-FFT + inv =========
__global__ __launch_bounds__(NT, 1)
void fft_conv_fused_kernel() {
    extern __shared__ char smem[];
    float2* sA     = (float2*)(smem);
    __half2* sH    = (__half2*)(smem + 131072);
    float2* sA1024 = (float2*)(smem + 196608);
    float2* sB256  = (float2*)(smem + 204800);
    float2* sW1024 = (float2*)(smem + 206848);
    float2* sT16   = (float2*)(smem + 208896);
    float2* sT4    = (float2*)(smem + 209024);
    float2* sK4    = (float2*)(smem + 209056);

    const int tid = threadIdx.x, d = blockIdx.x;

    // ---- table init ----
    for (int j = tid; j < 1024; j += NT) {
        float s, c;
        sincospif((float)j / 8192.0f, &s, &c);       // W^j = e^{-i pi j/8192}
        sA1024[j] = make_float2(c, -s);
    }
    if (tid < 256) {
        float s, c;
        sincospif((float)tid / 128.0f, &s, &c);      // W_256^j
        sB256[tid] = make_float2(c, -s);
        sincospif((float)tid / 512.0f, &s, &c);      // W_1024^j
        sW1024[tid] = make_float2(c, -s);
    }
    if (tid < 16) {
        float s, c;
        sincospif((float)tid / 32.0f, &s, &c);       // W_64^j
        sT16[tid] = make_float2(c, -s);
    }
    if (tid < 4) {
        float s, c;
        sincospif((float)tid / 8.0f, &s, &c);        // W_16^j == W^{1024j}
        sT4[tid] = make_float2(c, -s);
        sK4[tid] = make_float2(c, -s);
    }
    __syncthreads();

    // ================= h forward FFT -> sH (fp16) =================
    {
        const float* hp = g_ht + (size_t)d * DIML;
        #pragma unroll
        for (int g = 0; g < 2; g++) {
            const int t = tid + 512 * g;
            float2 v[4][4];
            #pragma unroll
            for (int a = 0; a < 4; a++)
                #pragma unroll
                for (int b = 0; b < 4; b++)
                    v[a][b] = (a < 2) ? make_float2(hp[t + 1024 * b + 4096 * a], 0.0f)
                                      : make_float2(0.0f, 0.0f);
            passA_fwd(v, sA1024, sK4, t);
            #pragma unroll
            for (int a = 0; a < 4; a++)
                #pragma unroll
                for (int b = 0; b < 4; b++)
                    sA[SWZ(t + 1024 * b + 4096 * a)] = v[a][b];
        }
        __syncthreads();
        passB_fwd(sA, sW1024, sB256, tid);
        passB_fwd(sA, sW1024, sB256, tid + 512);
        __syncthreads();
        passC_fwd(sA, sT16, tid);
        passC_fwd(sA, sT16, tid + 512);
        __syncthreads();
        #pragma unroll
        for (int g = 0; g < 2; g++) {
            const int t = tid + 512 * g;
            float2 u16[16];
            #pragma unroll
            for (int j = 0; j < 16; j++) u16[j] = sA[SWZ(16 * t + j)];
            passD_fwd(u16, sT4);
            #pragma unroll
            for (int j = 0; j < 16; j++)
                sH[j * 1024 + t] = __floats2half2_rn(u16[j].x, u16[j].y);
        }
    }
    __syncthreads();              // all pass-D reads of sA done before x reuses it

    // ================= x forward FFT, * H, inverse FFT =================
    {
        const float2* xp = g_xt + (size_t)d * DIML;
        #pragma unroll
        for (int g = 0; g < 2; g++) {
            const int t = tid + 512 * g;
            float2 v[4][4];
            #pragma unroll
            for (int a = 0; a < 4; a++)
                #pragma unroll
                for (int b = 0; b < 4; b++)
                    v[a][b] = (a < 2) ? xp[t + 1024 * b + 4096 * a] : make_float2(0.0f, 0.0f);
            passA_fwd(v, sA1024, sK4, t);
            #pragma unroll
            for (int a = 0; a < 4; a++)
                #pragma unroll
                for (int b = 0; b < 4; b++)
                    sA[SWZ(t + 1024 * b + 4096 * a)] = v[a][b];
        }
        __syncthreads();
        passB_fwd(sA, sW1024, sB256, tid);
        passB_fwd(sA, sW1024, sB256, tid + 512);
        __syncthreads();
        passC_fwd(sA, sT16, tid);
        passC_fwd(sA, sT16, tid + 512);
        __syncthreads();

        // pass D: fwd(4,1) + H multiply + inv(1,4)
        #pragma unroll
        for (int g = 0; g < 2; g++) {
            const int t = tid + 512 * g;
            float2 u16[16];
            #pragma unroll
            for (int j = 0; j < 16; j++) u16[j] = sA[SWZ(16 * t + j)];
            passD_fwd(u16, sT4);

            #pragma unroll
            for (int j = 0; j < 16; j++) {
                float2 hv = __half22float2(sH[j * 1024 + t]);
                u16[j] = cmul(u16[j], hv);
            }

            #pragma unroll
            for (int q = 0; q < 4; q++)
                ibfly(u16[4 * q], u16[4 * q + 1], u16[4 * q + 2], u16[4 * q + 3]);
            #pragma unroll
            for (int r = 0; r < 4; r++) {
                itw3(u16[r + 4], u16[r + 8], u16[r + 12], sT4[r]);
                ibfly(u16[r], u16[r + 4], u16[r + 8], u16[r + 12]);
            }
            #pragma unroll
            for (int j = 0; j < 16; j++) sA[SWZ(16 * t + j)] = u16[j];
        }
        __syncthreads();

        passC_inv(sA, sT16, tid);
        passC_inv(sA, sT16, tid + 512);
        __syncthreads();
        passB_inv(sA, sW1024, sB256, tid);
        passB_inv(sA, sW1024, sB256, tid + 512);
        __syncthreads();

        // pass A': inverse stages 1024 then 4096, scale + store
        const float scale = 1.0f / (float)NFFT;
        float2* yp = g_ys + (size_t)d * DIML;
        #pragma unroll
        for (int g = 0; g < 2; g++) {
            const int t = tid + 512 * g;
            float2 v[4][4];
            #pragma unroll
            for (int a = 0; a < 4; a++)
                #pragma unroll
                for (int b = 0; b < 4; b++)
                    v[a][b] = sA[SWZ(t + 1024 * b + 4096 * a)];
            const float2 at = sA1024[t];
            float2 w1 = cmul(at, at); w1 = cmul(w1, w1);   // at^4
            w1 = cconj(w1);
            float2 w2 = cmul(w1, w1), w3 = cmul(w1, w2);
            #pragma unroll
            for (int a = 0; a < 4; a++) {
                tw3w(v[a][1], v[a][2], v[a][3], w1, w2, w3);
                ibfly(v[a][0], v[a][1], v[a][2], v[a][3]);
            }
            #pragma unroll
            for (int b = 0; b < 4; b++) {
                float2 w = (b == 0) ? at : cmul(at, sK4[b]);
                itw3(v[1][b], v[2][b], v[3][b], w);
                ibfly(v[0][b], v[1][b], v[2][b], v[3][b]);
            }
            #pragma unroll
            for (int a = 0; a < 2; a++)
                #pragma unroll
                for (int b = 0; b < 4; b++) {
                    float2 r = v[a][b];
                    yp[t + 1024 * b + 4096 * a] = make_float2(r.x * scale, r.y * scale);
                }
        }
    }
}

// ---------------------------------------------------------------------------
extern "C" void kernel_launch(void* const* d_in, const int* in_sizes, int n_in,
                              void* d_out, int out_size) {
    const float* x    = (const float*)d_in[0];
    const float* h    = (const float*)d_in[1];
    const float* bias = (const float*)d_in[2];
    float* y = (float*)d_out;

    cudaFuncSetAttribute(fft_conv_fused_kernel,
                         cudaFuncAttributeMaxDynamicSharedMemorySize, SMEM_BYTES);

    transpose_x_kernel<<<dim3(DIMD / 32, DIML / 32), dim3(32, 8)>>>(x);
    transpose_h_kernel<<<dim3(DIMD / 32, DIML / 32), dim3(32, 8)>>>(h);
    fft_conv_fused_kernel<<<DIMD, NT, SMEM_BYTES>>>();
    transpose_out_kernel<<<dim3(DIML / 32, DIMD / 32), dim3(32, 8)>>>(bias, y);
}